// round 5
// baseline (speedup 1.0000x reference)
#include <cuda_runtime.h>
#include <cuda_bf16.h>

#define D_IN   128
#define D_OUT  64
#define NPAD   51200          // 25 * 2048, >= N
#define MAX_EDGES 1048576

// Scratch (device globals; zero-initialized at module load).
// Invariant: g_cnt is all-zero at kernel_launch entry (aggregate resets it).
__device__ float g_h[(size_t)NPAD * D_OUT];
__device__ int   g_cnt[NPAD];
__device__ int   g_row_ptr[NPAD];
__device__ int   g_fill_ptr[NPAD];
__device__ int   g_adj[MAX_EDGES];

// ---------------------------------------------------------------------------
// f32x2 packed helpers
// ---------------------------------------------------------------------------
__device__ __forceinline__ unsigned long long pk2(float a, float b) {
    unsigned long long r;
    asm("mov.b64 %0, {%1, %2};" : "=l"(r) : "f"(a), "f"(b));
    return r;
}
__device__ __forceinline__ void ffma2(unsigned long long& d,
                                      unsigned long long a,
                                      unsigned long long b) {
    asm("fma.rn.f32x2 %0, %1, %2, %3;" : "=l"(d) : "l"(a), "l"(b), "l"(d));
}
__device__ __forceinline__ float2 upk2(unsigned long long v) {
    float2 f;
    asm("mov.b64 {%0, %1}, %2;" : "=f"(f.x), "=f"(f.y) : "l"(v));
    return f;
}

// ---------------------------------------------------------------------------
// K1: GEMM h = x @ W^T + b  (f32x2 packed FMA)  +  fused in-degree histogram.
// The histogram atomics have unused returns -> REDG (fire-and-forget),
// hidden under the FFMA mainloop.
// ---------------------------------------------------------------------------
__global__ void __launch_bounds__(128) gemm_hist_kernel(
    const float* __restrict__ x, const float* __restrict__ W,
    const float* __restrict__ b, const int* __restrict__ row,
    int N, int E, int edges_per_block)
{
    __shared__ float4 xs[64][33];
    __shared__ float4 ws[64][33];

    const int tid = threadIdx.x;
    const int nb  = blockIdx.x * 64;

    // Fused histogram slice (fire-and-forget reductions)
    {
        int ebase = blockIdx.x * edges_per_block;
        for (int i = tid; i < edges_per_block; i += 128) {
            int e = ebase + i;
            if (e < E) atomicAdd(&g_cnt[__ldg(&row[e])], 1);
        }
    }

    const float4* W4 = (const float4*)W;
#pragma unroll
    for (int i = 0; i < 16; i++) {
        int lin = tid + 128 * i;
        int r = lin >> 5, c = lin & 31;
        ws[r][c] = W4[lin];
    }
    const float4* x4 = (const float4*)x;
#pragma unroll
    for (int i = 0; i < 16; i++) {
        int lin = tid + 128 * i;
        int r = lin >> 5, c = lin & 31;
        int node = nb + r;
        float4 v = make_float4(0.f, 0.f, 0.f, 0.f);
        if (node < N) v = x4[node * 32 + c];
        xs[r][c] = v;
    }
    __syncthreads();

    const int tx = tid & 15;
    const int ty = tid >> 4;

    unsigned long long acc[8][4];
#pragma unroll
    for (int i = 0; i < 8; i++)
#pragma unroll
        for (int j = 0; j < 4; j++) acc[i][j] = 0ull;

#pragma unroll 4
    for (int k = 0; k < 32; k++) {
        unsigned long long xlo[8], xhi[8], wlo[4], whi[4];
#pragma unroll
        for (int i = 0; i < 8; i++) {
            float4 v = xs[ty + 8 * i][k];
            xlo[i] = pk2(v.x, v.y);
            xhi[i] = pk2(v.z, v.w);
        }
#pragma unroll
        for (int j = 0; j < 4; j++) {
            float4 v = ws[tx + 16 * j][k];
            wlo[j] = pk2(v.x, v.y);
            whi[j] = pk2(v.z, v.w);
        }
#pragma unroll
        for (int i = 0; i < 8; i++) {
#pragma unroll
            for (int j = 0; j < 4; j++) {
                ffma2(acc[i][j], xlo[i], wlo[j]);
                ffma2(acc[i][j], xhi[i], whi[j]);
            }
        }
    }

    float bias[4];
#pragma unroll
    for (int j = 0; j < 4; j++) bias[j] = __ldg(&b[tx + 16 * j]);

#pragma unroll
    for (int i = 0; i < 8; i++) {
        int node = nb + ty + 8 * i;
        if (node < N) {
#pragma unroll
            for (int j = 0; j < 4; j++) {
                float2 p = upk2(acc[i][j]);
                g_h[(size_t)node * D_OUT + tx + 16 * j] = p.x + p.y + bias[j];
            }
        }
    }
}

// ---------------------------------------------------------------------------
// K2: single-block exclusive scan of g_cnt[0..NPAD) -> row_ptr, fill_ptr.
// 1024 threads, 25 tiles of 2048 (int2 per thread per tile).
// ---------------------------------------------------------------------------
__global__ void __launch_bounds__(1024) scan_kernel()
{
    __shared__ int wsum[32];
    const int tid = threadIdx.x, lane = tid & 31, w = tid >> 5;

    int carry = 0;
#pragma unroll 1
    for (int t = 0; t < NPAD / 2048; t++) {
        int idx = t * 2048 + tid * 2;
        int2 v = *(const int2*)&g_cnt[idx];
        int pair = v.x + v.y;

        int inc = pair;
#pragma unroll
        for (int off = 1; off < 32; off <<= 1) {
            int tt = __shfl_up_sync(~0u, inc, off);
            if (lane >= off) inc += tt;
        }
        if (lane == 31) wsum[w] = inc;
        __syncthreads();
        if (w == 0) {
            int s = wsum[lane];
#pragma unroll
            for (int off = 1; off < 32; off <<= 1) {
                int tt = __shfl_up_sync(~0u, s, off);
                if (lane >= off) s += tt;
            }
            wsum[lane] = s;
        }
        __syncthreads();

        int prefix = (w > 0 ? wsum[w - 1] : 0) + (inc - pair);
        int e0 = carry + prefix;
        int2 ev = make_int2(e0, e0 + v.x);
        *(int2*)&g_row_ptr[idx]  = ev;
        *(int2*)&g_fill_ptr[idx] = ev;

        carry += wsum[31];
        __syncthreads();
    }
}

// ---------------------------------------------------------------------------
// K3: fill adjacency (dense CSR)
// ---------------------------------------------------------------------------
__global__ void __launch_bounds__(256) fill_kernel(const int* __restrict__ row,
                                                   const int* __restrict__ col, int E)
{
    int e = blockIdx.x * blockDim.x + threadIdx.x;
    if (e >= E) return;
    int r = __ldg(&row[e]);
    int pos = atomicAdd(&g_fill_ptr[r], 1);
    g_adj[pos] = __ldg(&col[e]);
}

// ---------------------------------------------------------------------------
// K4: aggregate + normalize + write out + reset cnt (restores invariant).
// One warp per node; each lane owns one float2 (2 of 64 output dims).
// ---------------------------------------------------------------------------
__global__ void __launch_bounds__(256) aggregate_kernel(float* __restrict__ out, int N)
{
    int node = (blockIdx.x * blockDim.x + threadIdx.x) >> 5;
    int lane = threadIdx.x & 31;
    if (node >= N) return;

    int start = __ldg(&g_row_ptr[node]);
    int deg   = __ldg(&g_cnt[node]);
    if (lane == 0) g_cnt[node] = 0;   // restore invariant for next call

    const float2* h2 = (const float2*)g_h;
    float2 acc = make_float2(0.f, 0.f);

    int j = 0;
    for (; j + 4 <= deg; j += 4) {
        int c0 = __ldg(&g_adj[start + j]);
        int c1 = __ldg(&g_adj[start + j + 1]);
        int c2 = __ldg(&g_adj[start + j + 2]);
        int c3 = __ldg(&g_adj[start + j + 3]);
        float2 a0 = h2[c0 * 32 + lane];
        float2 a1 = h2[c1 * 32 + lane];
        float2 a2 = h2[c2 * 32 + lane];
        float2 a3 = h2[c3 * 32 + lane];
        acc.x += (a0.x + a1.x) + (a2.x + a3.x);
        acc.y += (a0.y + a1.y) + (a2.y + a3.y);
    }
    for (; j < deg; j++) {
        int c = __ldg(&g_adj[start + j]);
        float2 a = h2[c * 32 + lane];
        acc.x += a.x; acc.y += a.y;
    }

    float s = 1.0f / fmaxf((float)deg, 1.0f);
    acc.x *= s; acc.y *= s;
    ((float2*)out)[node * 32 + lane] = acc;
}

// ---------------------------------------------------------------------------
extern "C" void kernel_launch(void* const* d_in, const int* in_sizes, int n_in,
                              void* d_out, int out_size)
{
    const float* x   = (const float*)d_in[0];
    const float* W   = (const float*)d_in[1];
    const float* b   = (const float*)d_in[2];
    const int*   row = (const int*)d_in[3];
    const int*   col = (const int*)d_in[4];
    float* out = (float*)d_out;

    int N = in_sizes[0] / D_IN;   // 50000
    int E = in_sizes[3];          // 800000

    int gemm_blocks = (N + 63) / 64;                      // 782
    int epb = (E + gemm_blocks - 1) / gemm_blocks;        // ~1023

    gemm_hist_kernel<<<gemm_blocks, 128>>>(x, W, b, row, N, E, epb);
    scan_kernel<<<1, 1024>>>();
    fill_kernel<<<(E + 255) / 256, 256>>>(row, col, E);

    long long total = (long long)N * 32;
    aggregate_kernel<<<(int)((total + 255) / 256), 256>>>(out, N);
}

// round 7
// speedup vs baseline: 1.8161x; 1.8161x over previous
#include <cuda_runtime.h>
#include <cuda_fp16.h>
#include <cuda_bf16.h>

#define D_IN   128
#define D_OUT  64
#define MAX_NODES 65536      // padded (>= nchunks*1024)
#define MAX_EDGES 1048576
#define CHUNK 1024

// Scratch (device globals; zero-initialized at module load)
__device__ __half g_h[(size_t)MAX_NODES * D_OUT];   // fp16 projected features
__device__ int    g_cnt[MAX_NODES];
__device__ int    g_row_ptr[MAX_NODES];
__device__ int    g_fill_ptr[MAX_NODES];
__device__ int    g_adj[MAX_EDGES];
__device__ int    g_chunk_base[256];

// ---------------------------------------------------------------------------
// f32x2 packed helpers
// ---------------------------------------------------------------------------
__device__ __forceinline__ unsigned long long pk2(float a, float b) {
    unsigned long long r;
    asm("mov.b64 %0, {%1, %2};" : "=l"(r) : "f"(a), "f"(b));
    return r;
}
__device__ __forceinline__ void ffma2(unsigned long long& d,
                                      unsigned long long a,
                                      unsigned long long b) {
    asm("fma.rn.f32x2 %0, %1, %2, %3;" : "=l"(d) : "l"(a), "l"(b), "l"(d));
}
__device__ __forceinline__ float2 upk2(unsigned long long v) {
    float2 f;
    asm("mov.b64 {%0, %1}, %2;" : "=f"(f.x), "=f"(f.y) : "l"(v));
    return f;
}

// ---------------------------------------------------------------------------
// K0: zero histogram counters
// ---------------------------------------------------------------------------
__global__ void zero_cnt_kernel(int npad) {
    int i = blockIdx.x * blockDim.x + threadIdx.x;
    if (i < npad) g_cnt[i] = 0;
}

// ---------------------------------------------------------------------------
// K1: in-degree histogram (fire-and-forget REDG)
// ---------------------------------------------------------------------------
__global__ void hist_kernel(const int* __restrict__ row, int E) {
    int e = blockIdx.x * blockDim.x + threadIdx.x;
    if (e < E) atomicAdd(&g_cnt[__ldg(&row[e])], 1);
}

// ---------------------------------------------------------------------------
// K2a: per-chunk sums (256 threads x int4 = 1024 counts per block)
// ---------------------------------------------------------------------------
__global__ void __launch_bounds__(256) chunk_sum_kernel() {
    __shared__ int wsum[8];
    int tid = threadIdx.x, lane = tid & 31, w = tid >> 5;
    int base = blockIdx.x * CHUNK + tid * 4;
    int4 v = *(const int4*)&g_cnt[base];
    int s = v.x + v.y + v.z + v.w;
#pragma unroll
    for (int off = 16; off > 0; off >>= 1) s += __shfl_down_sync(~0u, s, off);
    if (lane == 0) wsum[w] = s;
    __syncthreads();
    if (tid == 0) {
        int t = 0;
#pragma unroll
        for (int i = 0; i < 8; i++) t += wsum[i];
        g_chunk_base[blockIdx.x] = t;
    }
}

// ---------------------------------------------------------------------------
// K2b: exclusive scan of chunk sums (single block, 64 threads, nchunks<=64)
// ---------------------------------------------------------------------------
__global__ void __launch_bounds__(64) scan_partials_kernel(int nchunks) {
    __shared__ int w0sum;
    int tid = threadIdx.x, lane = tid & 31, w = tid >> 5;
    int v = (tid < nchunks) ? g_chunk_base[tid] : 0;
    int x = v;
#pragma unroll
    for (int off = 1; off < 32; off <<= 1) {
        int t = __shfl_up_sync(~0u, x, off);
        if (lane >= off) x += t;
    }
    if (w == 0 && lane == 31) w0sum = x;
    __syncthreads();
    if (w == 1) x += w0sum;
    if (tid < nchunks) g_chunk_base[tid] = x - v;   // exclusive
}

// ---------------------------------------------------------------------------
// K2c: per-chunk exclusive scan + base (shuffle scan; 4 elems/thread)
// ---------------------------------------------------------------------------
__global__ void __launch_bounds__(256) scan_chunk_kernel() {
    __shared__ int wsum[8];
    int tid = threadIdx.x, lane = tid & 31, w = tid >> 5;
    int base = blockIdx.x * CHUNK + tid * 4;
    int4 v = *(const int4*)&g_cnt[base];
    int tsum = v.x + v.y + v.z + v.w;

    int inc = tsum;
#pragma unroll
    for (int off = 1; off < 32; off <<= 1) {
        int t = __shfl_up_sync(~0u, inc, off);
        if (lane >= off) inc += t;
    }
    if (lane == 31) wsum[w] = inc;
    __syncthreads();
    if (w == 0 && lane < 8) {
        int x = wsum[lane];
#pragma unroll
        for (int off = 1; off < 8; off <<= 1) {
            int t = __shfl_up_sync(0xff, x, off);
            if (lane >= off) x += t;
        }
        wsum[lane] = x;   // inclusive per-warp prefix
    }
    __syncthreads();

    int prefix = (w > 0 ? wsum[w - 1] : 0) + (inc - tsum);
    int e0 = g_chunk_base[blockIdx.x] + prefix;
    int e1 = e0 + v.x, e2 = e1 + v.y, e3 = e2 + v.z;
    int4 ev = make_int4(e0, e1, e2, e3);
    *(int4*)&g_row_ptr[base]  = ev;
    *(int4*)&g_fill_ptr[base] = ev;
}

// ---------------------------------------------------------------------------
// K3: fill adjacency
// ---------------------------------------------------------------------------
__global__ void fill_kernel(const int* __restrict__ row,
                            const int* __restrict__ col, int E) {
    int e = blockIdx.x * blockDim.x + threadIdx.x;
    if (e >= E) return;
    int r = __ldg(&row[e]);
    int pos = atomicAdd(&g_fill_ptr[r], 1);
    g_adj[pos] = __ldg(&col[e]);
}

// ---------------------------------------------------------------------------
// K4: GEMM h = x @ W^T + b (f32x2 packed FMA), epilogue stores fp16.
// ---------------------------------------------------------------------------
__global__ void __launch_bounds__(128) gemm_kernel(
    const float* __restrict__ x, const float* __restrict__ W,
    const float* __restrict__ b, int N)
{
    __shared__ float4 xs[64][33];
    __shared__ float4 ws[64][33];

    const int tid = threadIdx.x;
    const int nb  = blockIdx.x * 64;

    const float4* W4 = (const float4*)W;
#pragma unroll
    for (int i = 0; i < 16; i++) {
        int lin = tid + 128 * i;
        int r = lin >> 5, c = lin & 31;
        ws[r][c] = W4[lin];
    }
    const float4* x4 = (const float4*)x;
#pragma unroll
    for (int i = 0; i < 16; i++) {
        int lin = tid + 128 * i;
        int r = lin >> 5, c = lin & 31;
        int node = nb + r;
        float4 v = make_float4(0.f, 0.f, 0.f, 0.f);
        if (node < N) v = x4[node * 32 + c];
        xs[r][c] = v;
    }
    __syncthreads();

    const int tx = tid & 15;
    const int ty = tid >> 4;

    unsigned long long acc[8][4];
#pragma unroll
    for (int i = 0; i < 8; i++)
#pragma unroll
        for (int j = 0; j < 4; j++) acc[i][j] = 0ull;

#pragma unroll 4
    for (int k = 0; k < 32; k++) {
        unsigned long long xlo[8], xhi[8], wlo[4], whi[4];
#pragma unroll
        for (int i = 0; i < 8; i++) {
            float4 v = xs[ty + 8 * i][k];
            xlo[i] = pk2(v.x, v.y);
            xhi[i] = pk2(v.z, v.w);
        }
#pragma unroll
        for (int j = 0; j < 4; j++) {
            float4 v = ws[tx + 16 * j][k];
            wlo[j] = pk2(v.x, v.y);
            whi[j] = pk2(v.z, v.w);
        }
#pragma unroll
        for (int i = 0; i < 8; i++) {
#pragma unroll
            for (int j = 0; j < 4; j++) {
                ffma2(acc[i][j], xlo[i], wlo[j]);
                ffma2(acc[i][j], xhi[i], whi[j]);
            }
        }
    }

    float bias[4];
#pragma unroll
    for (int j = 0; j < 4; j++) bias[j] = __ldg(&b[tx + 16 * j]);

#pragma unroll
    for (int i = 0; i < 8; i++) {
        int node = nb + ty + 8 * i;
        if (node < N) {
#pragma unroll
            for (int j = 0; j < 4; j++) {
                float2 p = upk2(acc[i][j]);
                g_h[(size_t)node * D_OUT + tx + 16 * j] =
                    __float2half(p.x + p.y + bias[j]);
            }
        }
    }
}

// ---------------------------------------------------------------------------
// K5: aggregate + normalize + write out.
// One warp per node; each lane owns one __half2 (2 of 64 output dims).
// Each gather = exactly one 128B line per warp. 8-deep MLP.
// adj loaded with scalar LDG (CSR offsets are not 16B-aligned).
// ---------------------------------------------------------------------------
__global__ void __launch_bounds__(256) aggregate_kernel(float* __restrict__ out, int N)
{
    int node = (blockIdx.x * blockDim.x + threadIdx.x) >> 5;
    int lane = threadIdx.x & 31;
    if (node >= N) return;

    int start = __ldg(&g_row_ptr[node]);
    int deg   = __ldg(&g_cnt[node]);

    const __half2* h2 = (const __half2*)g_h;
    float2 acc = make_float2(0.f, 0.f);

    int j = 0;
    for (; j + 8 <= deg; j += 8) {
        int c0 = __ldg(&g_adj[start + j]);
        int c1 = __ldg(&g_adj[start + j + 1]);
        int c2 = __ldg(&g_adj[start + j + 2]);
        int c3 = __ldg(&g_adj[start + j + 3]);
        int c4 = __ldg(&g_adj[start + j + 4]);
        int c5 = __ldg(&g_adj[start + j + 5]);
        int c6 = __ldg(&g_adj[start + j + 6]);
        int c7 = __ldg(&g_adj[start + j + 7]);
        __half2 v0 = h2[c0 * 32 + lane];
        __half2 v1 = h2[c1 * 32 + lane];
        __half2 v2 = h2[c2 * 32 + lane];
        __half2 v3 = h2[c3 * 32 + lane];
        __half2 v4 = h2[c4 * 32 + lane];
        __half2 v5 = h2[c5 * 32 + lane];
        __half2 v6 = h2[c6 * 32 + lane];
        __half2 v7 = h2[c7 * 32 + lane];
        float2 f0 = __half22float2(v0), f1 = __half22float2(v1);
        float2 f2 = __half22float2(v2), f3 = __half22float2(v3);
        float2 f4 = __half22float2(v4), f5 = __half22float2(v5);
        float2 f6 = __half22float2(v6), f7 = __half22float2(v7);
        acc.x += ((f0.x + f1.x) + (f2.x + f3.x)) + ((f4.x + f5.x) + (f6.x + f7.x));
        acc.y += ((f0.y + f1.y) + (f2.y + f3.y)) + ((f4.y + f5.y) + (f6.y + f7.y));
    }
    for (; j < deg; j++) {
        int c = __ldg(&g_adj[start + j]);
        float2 f = __half22float2(h2[c * 32 + lane]);
        acc.x += f.x; acc.y += f.y;
    }

    float d = fmaxf((float)deg, 1.0f);
    acc.x /= d; acc.y /= d;
    ((float2*)out)[node * 32 + lane] = acc;
}

// ---------------------------------------------------------------------------
extern "C" void kernel_launch(void* const* d_in, const int* in_sizes, int n_in,
                              void* d_out, int out_size)
{
    const float* x   = (const float*)d_in[0];
    const float* W   = (const float*)d_in[1];
    const float* b   = (const float*)d_in[2];
    const int*   row = (const int*)d_in[3];
    const int*   col = (const int*)d_in[4];
    float* out = (float*)d_out;

    int N = in_sizes[0] / D_IN;   // 50000
    int E = in_sizes[3];          // 800000

    int nchunks = (N + CHUNK - 1) / CHUNK;   // 49
    int npad = nchunks * CHUNK;              // 50176

    zero_cnt_kernel<<<(npad + 255) / 256, 256>>>(npad);
    hist_kernel<<<(E + 255) / 256, 256>>>(row, E);
    chunk_sum_kernel<<<nchunks, 256>>>();
    scan_partials_kernel<<<1, 64>>>(nchunks);
    scan_chunk_kernel<<<nchunks, 256>>>();
    fill_kernel<<<(E + 255) / 256, 256>>>(row, col, E);
    gemm_kernel<<<(N + 63) / 64, 128>>>(x, W, b, N);

    long long total = (long long)N * 32;
    aggregate_kernel<<<(int)((total + 255) / 256), 256>>>(out, N);
}